// round 10
// baseline (speedup 1.0000x reference)
#include <cuda_runtime.h>
#include <cuda_bf16.h>

// ---------------------------------------------------------------------------
// 18-qubit statevector fidelity |<psi2|psi1>|^2, hardware-efficient ansatz.
// R10: f32x2 packed over adjacent-amp bit (amp bit 0), SoA re/im planes.
// Each thread: 8 amps = 4 packs (u64 re + u64 im per pack). Gates:
//   passA: q0 within-pack, q1,q2 reg, q3-7 packed shfl | T | q8 reg
//   passB: q9,q10 reg, q11-15 packed shfl | T | q16,q17 reg + CZ
// All coefficients duplicated+pre-negated in smem -> gates are pure
// mul/fma.rn.f32x2 chains (16 FFMA2 per pack-pair, zero ALU).
// ---------------------------------------------------------------------------

#define NQ 18
#define NL 6
#define NSTATE (1 << NQ)

typedef unsigned long long u64;

__device__ float d_re[2][NSTATE];
__device__ float d_im[2][NSTATE];
// per (s,l,q), SHFL-ordered dup12:
// [0-5]  lo: m00x m00y -m00y m01x m01y -m01y   (all duplicated (v,v))
// [6-11] hi: m11x m11y -m11y m10x m10y -m10y
__device__ u64 d_g12[2][NL][NQ][12];
// within-pack (q0) mixed coeffs per (s,l): C1 C2p nC2p C3 C4p nC4p
__device__ u64 d_w0[2][NL][6];
__device__ double d_acc[2];

// ---- packed helpers -------------------------------------------------------
__device__ __forceinline__ u64 f2pack(float lo, float hi) {
    u64 r;
    asm("mov.b64 %0, {%1, %2};" : "=l"(r) : "f"(lo), "f"(hi));
    return r;
}
__device__ __forceinline__ void f2unpack(u64 a, float& lo, float& hi) {
    asm("mov.b64 {%0, %1}, %2;" : "=f"(lo), "=f"(hi) : "l"(a));
}
__device__ __forceinline__ u64 fma2(u64 a, u64 b, u64 c) {
    u64 d;
    asm("fma.rn.f32x2 %0, %1, %2, %3;" : "=l"(d) : "l"(a), "l"(b), "l"(c));
    return d;
}
__device__ __forceinline__ u64 mul2(u64 a, u64 b) {
    u64 d;
    asm("mul.rn.f32x2 %0, %1, %2;" : "=l"(d) : "l"(a), "l"(b));
    return d;
}

__device__ __forceinline__ float2 cmulh(float2 a, float2 b) {
    return make_float2(a.x * b.x - a.y * b.y, a.x * b.y + a.y * b.x);
}
__device__ __forceinline__ float2 caddh(float2 a, float2 b) {
    return make_float2(a.x + b.x, a.y + b.y);
}
__device__ __forceinline__ float2 rscaleh(float r, float2 v) {
    return make_float2(r * v.x, r * v.y);
}

__global__ void qk_prep(const float* __restrict__ x1, const float* __restrict__ x2,
                        const float* __restrict__ iscale, const float* __restrict__ var) {
    int t = threadIdx.x;
    if (t < 2) d_acc[t] = 0.0;
    if (t >= 2 * NL * NQ) return;
    int s = t / (NL * NQ);
    int r = t % (NL * NQ);
    int l = r / NQ;
    int q = r % NQ;
    const float* x = s ? x2 : x1;

    float a = iscale[l * NQ + q] * x[q];
    float b = var[l * 2 * NQ + q];
    float c = var[l * 2 * NQ + NQ + q];

    float sa, ca, sb, cb, sc, cc;
    sincosf(0.5f * a, &sa, &ca);
    sincosf(0.5f * b, &sb, &cb);
    sincosf(0.5f * c, &sc, &cc);

    float2 X00 = make_float2(ca, 0.f), X01 = make_float2(0.f, -sa);
    float2 X10 = make_float2(0.f, -sa), X11 = make_float2(ca, 0.f);
    float2 M100 = caddh(rscaleh(cb, X00), rscaleh(-sb, X10));
    float2 M101 = caddh(rscaleh(cb, X01), rscaleh(-sb, X11));
    float2 M110 = caddh(rscaleh(sb, X00), rscaleh(cb, X10));
    float2 M111 = caddh(rscaleh(sb, X01), rscaleh(cb, X11));
    float2 e0 = make_float2(cc, -sc);
    float2 e1 = make_float2(cc, sc);
    float2 m00 = cmulh(e0, M100);
    float2 m01 = cmulh(e0, M101);
    float2 m10 = cmulh(e1, M110);
    float2 m11 = cmulh(e1, M111);

    u64* g = d_g12[s][l][q];
    g[0] = f2pack(m00.x, m00.x);
    g[1] = f2pack(m00.y, m00.y);
    g[2] = f2pack(-m00.y, -m00.y);
    g[3] = f2pack(m01.x, m01.x);
    g[4] = f2pack(m01.y, m01.y);
    g[5] = f2pack(-m01.y, -m01.y);
    g[6] = f2pack(m11.x, m11.x);
    g[7] = f2pack(m11.y, m11.y);
    g[8] = f2pack(-m11.y, -m11.y);
    g[9] = f2pack(m10.x, m10.x);
    g[10] = f2pack(m10.y, m10.y);
    g[11] = f2pack(-m10.y, -m10.y);
    if (q == 0) {
        u64* wv = d_w0[s][l];
        wv[0] = f2pack(m00.x, m11.x);
        wv[1] = f2pack(m00.y, m11.y);
        wv[2] = f2pack(-m00.y, -m11.y);
        wv[3] = f2pack(m01.x, m10.x);
        wv[4] = f2pack(m01.y, m10.y);
        wv[5] = f2pack(-m01.y, -m10.y);
    }
}

// between-pack gate on pack pair (A,B); g = SHFL-ordered dup12
__device__ __forceinline__ void gate_between(u64& Are, u64& Aim, u64& Bre, u64& Bim,
                                             const u64* g) {
    u64 m00x = g[0], m00y = g[1], nm00y = g[2];
    u64 m01x = g[3], m01y = g[4], nm01y = g[5];
    u64 m11x = g[6], m11y = g[7], nm11y = g[8];
    u64 m10x = g[9], m10y = g[10], nm10y = g[11];
    u64 nAre = fma2(m01x, Bre, fma2(nm01y, Bim, fma2(nm00y, Aim, mul2(m00x, Are))));
    u64 nAim = fma2(m01x, Bim, fma2(m01y, Bre, fma2(m00y, Are, mul2(m00x, Aim))));
    u64 nBre = fma2(m11x, Bre, fma2(nm11y, Bim, fma2(nm10y, Aim, mul2(m10x, Are))));
    u64 nBim = fma2(m11x, Bim, fma2(m11y, Bre, fma2(m10y, Are, mul2(m10x, Aim))));
    Are = nAre; Aim = nAim; Bre = nBre; Bim = nBim;
}

// within-pack gate (q0): c = [C1, C2p, nC2p, C3, C4p, nC4p]
__device__ __forceinline__ void gate_within(u64& Pre, u64& Pim, const u64* c) {
    float rlo, rhi, ilo, ihi;
    f2unpack(Pre, rlo, rhi);
    f2unpack(Pim, ilo, ihi);
    u64 rsw = f2pack(rhi, rlo);
    u64 isw = f2pack(ihi, ilo);
    u64 nre = fma2(c[3], rsw, fma2(c[5], isw, fma2(c[2], Pim, mul2(c[0], Pre))));
    u64 nim = fma2(c[3], isw, fma2(c[4], rsw, fma2(c[1], Pre, mul2(c[0], Pim))));
    Pre = nre; Pim = nim;
}

// packed shfl gate on one pack; c = 6 coeffs chosen by lane side
__device__ __forceinline__ void gate_shflp(u64& vre, u64& vim, int mask, const u64* c) {
    u64 pre = __shfl_xor_sync(0xFFFFFFFFu, vre, mask);
    u64 pim = __shfl_xor_sync(0xFFFFFFFFu, vim, mask);
    u64 nre = fma2(c[3], pre, fma2(c[5], pim, fma2(c[2], vim, mul2(c[0], vre))));
    u64 nim = fma2(c[3], pim, fma2(c[4], pre, fma2(c[1], vre, mul2(c[0], vim))));
    vre = nre; vim = nim;
}

// swizzle over 9-bit pack index: fold bits 4,5 into 0,1
__device__ __forceinline__ unsigned swz(unsigned p) {
    return p ^ ((p >> 4) & 3u);
}

#define SHFL_GATE_P(j, mask)                                                  \
    {                                                                         \
        const u64* c = sG + 12 * (j) + ((lane & (mask)) ? 6 : 0);             \
        gate_shflp(Pre[0], Pim[0], (mask), c);                                \
        gate_shflp(Pre[1], Pim[1], (mask), c);                                \
        gate_shflp(Pre[2], Pim[2], (mask), c);                                \
        gate_shflp(Pre[3], Pim[3], (mask), c);                                \
    }

// ---------------------------------------------------------------------------
// passA: qubits 0..8. 512 blocks x 128 thr, 8 amps = 4 packs/thread.
// Window = amp bits 0-9 (1024 amps, 512 packs); pack bit = amp bit 0.
// Pack index p (9 bits) = amp bits 1-9.
// m1: p = k | lane<<2 | w<<7 -> q0 within; q1,q2 reg (k); q3-7 shfl (lane)
// m2: p = lane | w<<5 | k<<7 -> q8 reg (k bit0); k bit1 = amp bit 9 rider
// ---------------------------------------------------------------------------
__global__ void __launch_bounds__(128) qk_passA(int layer, int init) {
    __shared__ u64 sm_re[512];
    __shared__ u64 sm_im[512];
    __shared__ u64 sG[108];
    __shared__ u64 sW[6];
    int tid = threadIdx.x;
    int lane = tid & 31;
    unsigned w = (unsigned)(tid >> 5);              // 0..3
    int blk = blockIdx.x;
    int s = blk >> 8;
    unsigned ubase = ((unsigned)(blk & 255)) << 9;  // u64-plane base (packs)
    u64* re64 = (u64*)d_re[s];
    u64* im64 = (u64*)d_im[s];

    if (tid < 108) sG[tid] = (&d_g12[s][layer][0][0])[tid];
    if (tid >= 112 && tid < 118) sW[tid - 112] = d_w0[s][layer][tid - 112];

    unsigned p1 = ((unsigned)lane << 2) | (w << 7);
    u64 Pre[4], Pim[4];

    if (init) {
        Pre[0] = Pre[1] = Pre[2] = Pre[3] = 0ull;
        Pim[0] = Pim[1] = Pim[2] = Pim[3] = 0ull;
        if ((ubase | p1) == 0) Pre[0] = f2pack(1.f, 0.f);
    } else {
        ulonglong2 ra = *(const ulonglong2*)(re64 + ubase + p1);
        ulonglong2 rb = *(const ulonglong2*)(re64 + ubase + p1 + 2);
        ulonglong2 ia = *(const ulonglong2*)(im64 + ubase + p1);
        ulonglong2 ib = *(const ulonglong2*)(im64 + ubase + p1 + 2);
        Pre[0] = ra.x; Pre[1] = ra.y; Pre[2] = rb.x; Pre[3] = rb.y;
        Pim[0] = ia.x; Pim[1] = ia.y; Pim[2] = ib.x; Pim[3] = ib.y;
    }
    __syncthreads();                                // sG/sW ready

    // q0: within-pack
    gate_within(Pre[0], Pim[0], sW);
    gate_within(Pre[1], Pim[1], sW);
    gate_within(Pre[2], Pim[2], sW);
    gate_within(Pre[3], Pim[3], sW);
    // q1 (p bit 0), q2 (p bit 1): between packs
    gate_between(Pre[0], Pim[0], Pre[1], Pim[1], sG + 12);
    gate_between(Pre[2], Pim[2], Pre[3], Pim[3], sG + 12);
    gate_between(Pre[0], Pim[0], Pre[2], Pim[2], sG + 24);
    gate_between(Pre[1], Pim[1], Pre[3], Pim[3], sG + 24);
    // q3..q7: packed shfl (lane bits 0-4)
    SHFL_GATE_P(3, 1)
    SHFL_GATE_P(4, 2)
    SHFL_GATE_P(5, 4)
    SHFL_GATE_P(6, 8)
    SHFL_GATE_P(7, 16)

    // transpose
    unsigned sb1 = swz(p1);
#pragma unroll
    for (int k = 0; k < 4; k++) {
        sm_re[sb1 ^ (unsigned)k] = Pre[k];
        sm_im[sb1 ^ (unsigned)k] = Pim[k];
    }
    __syncthreads();

    unsigned p2 = (unsigned)lane | (w << 5);
    unsigned sb2 = swz(p2);
#pragma unroll
    for (int k = 0; k < 4; k++) {
        Pre[k] = sm_re[sb2 + ((unsigned)k << 7)];
        Pim[k] = sm_im[sb2 + ((unsigned)k << 7)];
    }

    // q8 (p bit 7 = k bit 0): between packs; k bit 1 = amp bit 9 rider
    gate_between(Pre[0], Pim[0], Pre[1], Pim[1], sG + 96);
    gate_between(Pre[2], Pim[2], Pre[3], Pim[3], sG + 96);

    // stores: lanes cover 32 consecutive u64 = 256B contiguous per k
#pragma unroll
    for (int k = 0; k < 4; k++) {
        re64[ubase + p2 + ((unsigned)k << 7)] = Pre[k];
        im64[ubase + p2 + ((unsigned)k << 7)] = Pim[k];
    }
}

// ---------------------------------------------------------------------------
// passB: qubits 9..17 + CZ. Window = amp bits {0, 9-17}; pack bit = amp bit 0.
// Pack index p (9 bits) = amp bits 9-17; rest (blk&255) = amp bits 1-8.
// u64-plane index of pack p = rest | p<<8.
// m1: p = k | lane<<2 | w<<7 -> q9,q10 reg (k); q11-15 shfl (lane)
// m2: p = lane | w<<5 | k<<7 -> q16 (k bit0), q17 (k bit1) reg
// ---------------------------------------------------------------------------
__global__ void __launch_bounds__(128) qk_passB(int layer) {
    __shared__ u64 sm_re[512];
    __shared__ u64 sm_im[512];
    __shared__ u64 sG[108];
    int tid = threadIdx.x;
    int lane = tid & 31;
    unsigned w = (unsigned)(tid >> 5);
    int blk = blockIdx.x;
    int s = blk >> 8;
    unsigned rest = (unsigned)(blk & 255);
    u64* re64 = (u64*)d_re[s];
    u64* im64 = (u64*)d_im[s];

    if (tid < 108) sG[tid] = (&d_g12[s][layer][9][0])[tid];

    unsigned p1 = ((unsigned)lane << 2) | (w << 7);
    u64 Pre[4], Pim[4];
#pragma unroll
    for (int k = 0; k < 4; k++) {
        unsigned idx = rest | ((p1 + (unsigned)k) << 8);
        Pre[k] = re64[idx];
        Pim[k] = im64[idx];
    }
    __syncthreads();                                // sG ready

    // q9 (p bit 0), q10 (p bit 1): between packs
    gate_between(Pre[0], Pim[0], Pre[1], Pim[1], sG + 0);
    gate_between(Pre[2], Pim[2], Pre[3], Pim[3], sG + 0);
    gate_between(Pre[0], Pim[0], Pre[2], Pim[2], sG + 12);
    gate_between(Pre[1], Pim[1], Pre[3], Pim[3], sG + 12);
    // q11..q15: packed shfl (lane bits 0-4); sG index j = q-9
    SHFL_GATE_P(2, 1)
    SHFL_GATE_P(3, 2)
    SHFL_GATE_P(4, 4)
    SHFL_GATE_P(5, 8)
    SHFL_GATE_P(6, 16)

    unsigned sb1 = swz(p1);
#pragma unroll
    for (int k = 0; k < 4; k++) {
        sm_re[sb1 ^ (unsigned)k] = Pre[k];
        sm_im[sb1 ^ (unsigned)k] = Pim[k];
    }
    __syncthreads();

    unsigned p2 = (unsigned)lane | (w << 5);
    unsigned sb2 = swz(p2);
#pragma unroll
    for (int k = 0; k < 4; k++) {
        Pre[k] = sm_re[sb2 + ((unsigned)k << 7)];
        Pim[k] = sm_im[sb2 + ((unsigned)k << 7)];
    }

    // q16 (p bit 7 = k bit0), q17 (p bit 8 = k bit1): between packs
    gate_between(Pre[0], Pim[0], Pre[1], Pim[1], sG + 84);
    gate_between(Pre[2], Pim[2], Pre[3], Pim[3], sG + 84);
    gate_between(Pre[0], Pim[0], Pre[2], Pim[2], sG + 96);
    gate_between(Pre[1], Pim[1], Pre[3], Pim[3], sG + 96);

    // CZ chain sign + store
#pragma unroll
    for (int k = 0; k < 4; k++) {
        unsigned p = p2 + ((unsigned)k << 7);
        unsigned g0 = (rest << 1) | (p << 9);       // even amp of the pack
        unsigned tm = g0 & (g0 >> 1) & 0x1FFFFu;
        unsigned s0 = (unsigned)(__popc(tm) & 1);
        unsigned s1 = s0 ^ ((g0 >> 1) & 1u);
        u64 m = ((u64)(s0 << 31)) | (((u64)(s1 << 31)) << 32);
        Pre[k] ^= m;
        Pim[k] ^= m;
        unsigned idx = rest | (p << 8);
        re64[idx] = Pre[k];
        im64[idx] = Pim[k];
    }
}

// ---------------------------------------------------------------------------
// Overlap reduction (SoA): acc += conj(psi2) . psi1
// ---------------------------------------------------------------------------
__global__ void qk_reduce() {
    int t = blockIdx.x * blockDim.x + threadIdx.x;
    int nthreads = gridDim.x * blockDim.x;
    double re = 0.0, im = 0.0;
    for (int i = t; i < NSTATE; i += nthreads) {
        float ar = d_re[0][i], ai = d_im[0][i];
        float br = d_re[1][i], bi = d_im[1][i];
        re += (double)br * ar + (double)bi * ai;
        im += (double)br * ai - (double)bi * ar;
    }
#pragma unroll
    for (int o = 16; o > 0; o >>= 1) {
        re += __shfl_down_sync(0xFFFFFFFFu, re, o);
        im += __shfl_down_sync(0xFFFFFFFFu, im, o);
    }
    if ((threadIdx.x & 31) == 0) {
        atomicAdd(&d_acc[0], re);
        atomicAdd(&d_acc[1], im);
    }
}

__global__ void qk_final(float* out) {
    double re = d_acc[0], im = d_acc[1];
    out[0] = (float)(re * re + im * im);
}

extern "C" void kernel_launch(void* const* d_in, const int* in_sizes, int n_in,
                              void* d_out, int out_size) {
    const float* x1 = (const float*)d_in[0];
    const float* x2 = (const float*)d_in[1];
    const float* iscale = (const float*)d_in[2];
    const float* var = (const float*)d_in[3];

    qk_prep<<<1, 256>>>(x1, x2, iscale, var);
    for (int l = 0; l < NL; l++) {
        qk_passA<<<512, 128>>>(l, l == 0 ? 1 : 0);
        qk_passB<<<512, 128>>>(l);
    }
    qk_reduce<<<148, 256>>>();
    qk_final<<<1, 1>>>((float*)d_out);
}

// round 11
// speedup vs baseline: 1.5790x; 1.5790x over previous
#include <cuda_runtime.h>
#include <cuda_bf16.h>

// ---------------------------------------------------------------------------
// 18-qubit statevector fidelity |<psi2|psi1>|^2, hardware-efficient ansatz.
// R11: cross-layer staircase fusion -> 7 pass kernels total (was 12).
// CZ is diagonal: its sign depends only on the global amp index, so a full
// CZ-chain can be applied in ANY pass at the point where layer l's gates are
// all complete. Schedule (A = window bits 0-9, B = window {0,1,10-17}):
//   P1 A: G0(0-9)                      P2 B: G0(10-17), CZ0, G1(10-17)
//   P3 A: G1(0-9),  CZ1, G2(0-9)       P4 B: G2(10-17), CZ2, G3(10-17)
//   P5 A: G3(0-9),  CZ3, G4(0-9)       P6 B: G4(10-17), CZ4, G5(10-17)
//   P7 A: G5(0-9),  CZ5
// Mid passes do two G-rounds with 3 smem transposes (R7's verified swizzle;
// the transpose-back patterns are the mirrors of the verified ones).
// Gate math identical to R7 (best known: explicit fmaf chains, smem-staged
// matrices, coalescing-fixed mapping 2).
// ---------------------------------------------------------------------------

#define NQ 18
#define NL 6
#define NSTATE (1 << NQ)

__device__ float2 d_psi[2][NSTATE];
// per (s,l,q): f4[0]=(m00.x,m00.y,m01.x,m01.y), f4[1]=(m10.x,m10.y,m11.x,m11.y)
__device__ float4 d_mats[2][NL][NQ][2];
__device__ double d_acc[2];

__device__ __forceinline__ float2 cmulh(float2 a, float2 b) {
    return make_float2(a.x * b.x - a.y * b.y, a.x * b.y + a.y * b.x);
}
__device__ __forceinline__ float2 caddh(float2 a, float2 b) {
    return make_float2(a.x + b.x, a.y + b.y);
}
__device__ __forceinline__ float2 rscaleh(float r, float2 v) {
    return make_float2(r * v.x, r * v.y);
}

__global__ void qk_prep(const float* __restrict__ x1, const float* __restrict__ x2,
                        const float* __restrict__ iscale, const float* __restrict__ var) {
    int t = threadIdx.x;
    if (t < 2) d_acc[t] = 0.0;
    if (t >= 2 * NL * NQ) return;
    int s = t / (NL * NQ);
    int r = t % (NL * NQ);
    int l = r / NQ;
    int q = r % NQ;
    const float* x = s ? x2 : x1;

    float a = iscale[l * NQ + q] * x[q];
    float b = var[l * 2 * NQ + q];
    float c = var[l * 2 * NQ + NQ + q];

    float sa, ca, sb, cb, sc, cc;
    sincosf(0.5f * a, &sa, &ca);
    sincosf(0.5f * b, &sb, &cb);
    sincosf(0.5f * c, &sc, &cc);

    float2 X00 = make_float2(ca, 0.f), X01 = make_float2(0.f, -sa);
    float2 X10 = make_float2(0.f, -sa), X11 = make_float2(ca, 0.f);
    float2 M100 = caddh(rscaleh(cb, X00), rscaleh(-sb, X10));
    float2 M101 = caddh(rscaleh(cb, X01), rscaleh(-sb, X11));
    float2 M110 = caddh(rscaleh(sb, X00), rscaleh(cb, X10));
    float2 M111 = caddh(rscaleh(sb, X01), rscaleh(cb, X11));
    float2 e0 = make_float2(cc, -sc);
    float2 e1 = make_float2(cc, sc);
    float2 m00 = cmulh(e0, M100);
    float2 m01 = cmulh(e0, M101);
    float2 m10 = cmulh(e1, M110);
    float2 m11 = cmulh(e1, M111);

    d_mats[s][l][q][0] = make_float4(m00.x, m00.y, m01.x, m01.y);
    d_mats[s][l][q][1] = make_float4(m10.x, m10.y, m11.x, m11.y);
}

__device__ __forceinline__ void gate_pair(float2& a, float2& b, float4 c0, float4 c1) {
    float nax = fmaf(c0.z, b.x, fmaf(-c0.w, b.y, fmaf(c0.x, a.x, -c0.y * a.y)));
    float nay = fmaf(c0.z, b.y, fmaf(c0.w, b.x, fmaf(c0.x, a.y, c0.y * a.x)));
    float nbx = fmaf(c1.z, b.x, fmaf(-c1.w, b.y, fmaf(c1.x, a.x, -c1.y * a.y)));
    float nby = fmaf(c1.z, b.y, fmaf(c1.w, b.x, fmaf(c1.x, a.y, c1.y * a.x)));
    a = make_float2(nax, nay);
    b = make_float2(nbx, nby);
}

__device__ __forceinline__ float2 gate_shfl(float2 v, int mask,
                                            float cax, float cay, float cbx, float cby) {
    float px = __shfl_xor_sync(0xFFFFFFFFu, v.x, mask);
    float py = __shfl_xor_sync(0xFFFFFFFFu, v.y, mask);
    float rx = fmaf(cbx, px, fmaf(-cby, py, fmaf(cax, v.x, -cay * v.y)));
    float ry = fmaf(cbx, py, fmaf(cby, px, fmaf(cax, v.y, cay * v.x)));
    return make_float2(rx, ry);
}

// smem swizzle: fold amp bits 4,5 into bits 0,1 (R7, conflict-free both ways)
__device__ __forceinline__ unsigned swz(unsigned l) {
    return l ^ ((l >> 4) & 3u);
}

#define SHFL_GATE_M(M, j, mask)                                               \
    {                                                                         \
        float4 c0 = (M)[2 * (j)], c1 = (M)[2 * (j) + 1];                      \
        bool hi = (lane & (mask)) != 0;                                       \
        float cax = hi ? c1.z : c0.x;                                         \
        float cay = hi ? c1.w : c0.y;                                         \
        float cbx = hi ? c1.x : c0.z;                                         \
        float cby = hi ? c1.y : c0.w;                                         \
        _Pragma("unroll") for (int k = 0; k < 4; k++)                         \
            v[k] = gate_shfl(v[k], (mask), cax, cay, cbx, cby);               \
    }

// ---------------------------------------------------------------------------
// Window-A kernel: gates q0-9 for layer l1 (and l2 if >= 0), CZ sign (czf)
// applied after the l1 round. Mappings as R7 passA:
// m1: l = k | lane<<2 | w<<7 ; m2: l = (lane&15) | ((lane>>4)<<9) | w<<4 | k<<7
// ---------------------------------------------------------------------------
__global__ void __launch_bounds__(256) qk_A(int l1, int l2, int czf, int init) {
    __shared__ float2 sm[1024];
    __shared__ float4 sM[40];
    int tid = threadIdx.x;
    int lane = tid & 31;
    unsigned w = (unsigned)(tid >> 5);
    int blk = blockIdx.x;
    int s = blk >> 8;
    unsigned blkbase = ((unsigned)(blk & 255)) << 10;
    float2* psi = d_psi[s];

    if (tid < 20) sM[tid] = (&d_mats[s][l1][0][0])[tid];
    if (l2 >= 0 && tid >= 32 && tid < 52) sM[20 + tid - 32] = (&d_mats[s][l2][0][0])[tid - 32];

    unsigned l1i = ((unsigned)lane << 2) | (w << 7);
    unsigned base2 = ((unsigned)lane & 15u) | (((unsigned)lane >> 4) << 9) | (w << 4);
    float2 v[4];

    if (init) {
#pragma unroll
        for (int k = 0; k < 4; k++) v[k] = make_float2(0.f, 0.f);
        if ((blkbase | l1i) == 0) v[0] = make_float2(1.f, 0.f);
    } else {
        const float4* p4 = (const float4*)(psi + blkbase + l1i);
        float4 a = p4[0], b = p4[1];
        v[0] = make_float2(a.x, a.y);
        v[1] = make_float2(a.z, a.w);
        v[2] = make_float2(b.x, b.y);
        v[3] = make_float2(b.z, b.w);
    }
    __syncthreads();                                // sM ready

    int rounds = (l2 >= 0) ? 2 : 1;
    for (int r = 0; r < rounds; r++) {
        const float4* M = sM + (r ? 20 : 0);
        if (r) {                                    // transpose back m2 -> m1
            __syncthreads();
#pragma unroll
            for (int k = 0; k < 4; k++) sm[swz(base2) + ((unsigned)k << 7)] = v[k];
            __syncthreads();
#pragma unroll
            for (int k = 0; k < 4; k++) v[k] = sm[swz(l1i) ^ (unsigned)k];
        }
        // m1 gates: q0 (k stride 1), q1 (k stride 2), q2-6 (lane shfl)
        {
            float4 c0 = M[0], c1 = M[1];
            gate_pair(v[0], v[1], c0, c1);
            gate_pair(v[2], v[3], c0, c1);
        }
        {
            float4 c0 = M[2], c1 = M[3];
            gate_pair(v[0], v[2], c0, c1);
            gate_pair(v[1], v[3], c0, c1);
        }
        SHFL_GATE_M(M, 2, 1)
        SHFL_GATE_M(M, 3, 2)
        SHFL_GATE_M(M, 4, 4)
        SHFL_GATE_M(M, 5, 8)
        SHFL_GATE_M(M, 6, 16)

        // transpose m1 -> m2
        if (r) __syncthreads();                     // round-2: prior sm reads done
        unsigned sb1 = swz(l1i);
#pragma unroll
        for (int k = 0; k < 4; k++) sm[sb1 ^ (unsigned)k] = v[k];
        __syncthreads();
        unsigned sb2 = swz(base2);
#pragma unroll
        for (int k = 0; k < 4; k++) v[k] = sm[sb2 + ((unsigned)k << 7)];

        // m2 gates: q7 (k' stride 1), q8 (k' stride 2), q9 (lane bit 4 shfl)
        {
            float4 c0 = M[14], c1 = M[15];
            gate_pair(v[0], v[1], c0, c1);
            gate_pair(v[2], v[3], c0, c1);
        }
        {
            float4 c0 = M[16], c1 = M[17];
            gate_pair(v[0], v[2], c0, c1);
            gate_pair(v[1], v[3], c0, c1);
        }
        SHFL_GATE_M(M, 9, 16)

        // CZ chain sign after the l1 round
        if (r == 0 && czf >= 0) {
#pragma unroll
            for (int k = 0; k < 4; k++) {
                unsigned g = blkbase + base2 + ((unsigned)k << 7);
                unsigned tm = g & (g >> 1) & 0x1FFFFu;
                if (__popc(tm) & 1) {
                    v[k].x = -v[k].x;
                    v[k].y = -v[k].y;
                }
            }
        }
    }

    // store from m2 (coalesced: 16 lanes = 128B contiguous per k)
#pragma unroll
    for (int k = 0; k < 4; k++)
        psi[blkbase + base2 + ((unsigned)k << 7)] = v[k];
}

// ---------------------------------------------------------------------------
// Window-B kernel: gates q10-17 for layer l1 (and l2 if >= 0), CZ sign after
// the l1 round. Window = {0,1,10..17}; g(l) = (l&3) | rest<<2 | (l>>2)<<10.
// ---------------------------------------------------------------------------
__global__ void __launch_bounds__(256) qk_B(int l1, int l2, int czf) {
    __shared__ float2 sm[1024];
    __shared__ float4 sM[32];
    int tid = threadIdx.x;
    int lane = tid & 31;
    unsigned w = (unsigned)(tid >> 5);
    int blk = blockIdx.x;
    int s = blk >> 8;
    unsigned rest = (unsigned)(blk & 255);
    float2* psi = d_psi[s];

    if (tid < 16) sM[tid] = (&d_mats[s][l1][10][0])[tid];
    if (l2 >= 0 && tid >= 32 && tid < 48) sM[16 + tid - 32] = (&d_mats[s][l2][10][0])[tid - 32];

    unsigned l1i = ((unsigned)lane << 2) | (w << 7);
    unsigned g1 = (l1i & 3u) | (rest << 2) | ((l1i >> 2) << 10);
    unsigned base2 = ((unsigned)lane & 15u) | (((unsigned)lane >> 4) << 9) | (w << 4);

    float2 v[4];
    {
        const float4* p4 = (const float4*)(psi + g1);
        float4 a = p4[0], b = p4[1];
        v[0] = make_float2(a.x, a.y);
        v[1] = make_float2(a.z, a.w);
        v[2] = make_float2(b.x, b.y);
        v[3] = make_float2(b.z, b.w);
    }
    __syncthreads();                                // sM ready

    int rounds = (l2 >= 0) ? 2 : 1;
    for (int r = 0; r < rounds; r++) {
        const float4* M = sM + (r ? 16 : 0);
        if (r) {                                    // transpose back m2 -> m1
            __syncthreads();
#pragma unroll
            for (int k = 0; k < 4; k++) sm[swz(base2) + ((unsigned)k << 7)] = v[k];
            __syncthreads();
#pragma unroll
            for (int k = 0; k < 4; k++) v[k] = sm[swz(l1i) ^ (unsigned)k];
        }
        // m1 gates: q10..q14 (lane shfl; j = q-10)
        SHFL_GATE_M(M, 0, 1)
        SHFL_GATE_M(M, 1, 2)
        SHFL_GATE_M(M, 2, 4)
        SHFL_GATE_M(M, 3, 8)
        SHFL_GATE_M(M, 4, 16)

        if (r) __syncthreads();
        unsigned sb1 = swz(l1i);
#pragma unroll
        for (int k = 0; k < 4; k++) sm[sb1 ^ (unsigned)k] = v[k];
        __syncthreads();
        unsigned sb2 = swz(base2);
#pragma unroll
        for (int k = 0; k < 4; k++) v[k] = sm[sb2 + ((unsigned)k << 7)];

        // m2 gates: q15 (k' stride 1), q16 (k' stride 2), q17 (lane bit4 shfl)
        {
            float4 c0 = M[10], c1 = M[11];
            gate_pair(v[0], v[1], c0, c1);
            gate_pair(v[2], v[3], c0, c1);
        }
        {
            float4 c0 = M[12], c1 = M[13];
            gate_pair(v[0], v[2], c0, c1);
            gate_pair(v[1], v[3], c0, c1);
        }
        SHFL_GATE_M(M, 7, 16)

        if (r == 0 && czf >= 0) {
#pragma unroll
            for (int k = 0; k < 4; k++) {
                unsigned l2i = base2 | ((unsigned)k << 7);
                unsigned g = (l2i & 3u) | (rest << 2) | ((l2i >> 2) << 10);
                unsigned tm = g & (g >> 1) & 0x1FFFFu;
                if (__popc(tm) & 1) {
                    v[k].x = -v[k].x;
                    v[k].y = -v[k].y;
                }
            }
        }
    }

    // store (32B-sector aligned groups)
#pragma unroll
    for (int k = 0; k < 4; k++) {
        unsigned l2i = base2 | ((unsigned)k << 7);
        unsigned g = (l2i & 3u) | (rest << 2) | ((l2i >> 2) << 10);
        psi[g] = v[k];
    }
}

__global__ void qk_reduce() {
    int t = blockIdx.x * blockDim.x + threadIdx.x;
    int nthreads = gridDim.x * blockDim.x;
    double re = 0.0, im = 0.0;
    for (int i = t; i < NSTATE; i += nthreads) {
        float2 a = d_psi[0][i];
        float2 b = d_psi[1][i];
        re += (double)b.x * a.x + (double)b.y * a.y;
        im += (double)b.x * a.y - (double)b.y * a.x;
    }
#pragma unroll
    for (int o = 16; o > 0; o >>= 1) {
        re += __shfl_down_sync(0xFFFFFFFFu, re, o);
        im += __shfl_down_sync(0xFFFFFFFFu, im, o);
    }
    if ((threadIdx.x & 31) == 0) {
        atomicAdd(&d_acc[0], re);
        atomicAdd(&d_acc[1], im);
    }
}

__global__ void qk_final(float* out) {
    double re = d_acc[0], im = d_acc[1];
    out[0] = (float)(re * re + im * im);
}

extern "C" void kernel_launch(void* const* d_in, const int* in_sizes, int n_in,
                              void* d_out, int out_size) {
    const float* x1 = (const float*)d_in[0];
    const float* x2 = (const float*)d_in[1];
    const float* iscale = (const float*)d_in[2];
    const float* var = (const float*)d_in[3];

    qk_prep<<<1, 256>>>(x1, x2, iscale, var);
    qk_A<<<512, 256>>>(0, -1, -1, 1);               // G0(0-9), init
    qk_B<<<512, 256>>>(0, 1, 0);                    // G0(10-17), CZ0, G1(10-17)
    qk_A<<<512, 256>>>(1, 2, 1, 0);                 // G1(0-9),  CZ1, G2(0-9)
    qk_B<<<512, 256>>>(2, 3, 2);                    // G2(10-17), CZ2, G3(10-17)
    qk_A<<<512, 256>>>(3, 4, 3, 0);                 // G3(0-9),  CZ3, G4(0-9)
    qk_B<<<512, 256>>>(4, 5, 4);                    // G4(10-17), CZ4, G5(10-17)
    qk_A<<<512, 256>>>(5, -1, 5, 0);                // G5(0-9),  CZ5
    qk_reduce<<<148, 256>>>();
    qk_final<<<1, 1>>>((float*)d_out);
}